// round 9
// baseline (speedup 1.0000x reference)
#include <cuda_runtime.h>
#include <math.h>

// IterNormRotation, hardcoded shapes from setup_inputs():
//   X: (32, 512, 56, 56) fp32, rot: (1, 512, 512) fp32, T = 10.
// Pipeline:
//   S = X Xrowᵀ (Gram over m = B*H*W), sum_c = per-channel sums
//   Sigma = eps I + S/m - mu muᵀ ; rTr = 1/tr(Sigma); SN = Sigma*rTr; P = I
//   10x Newton-Schulz: P = 1.5 P - 0.5 (P@P)@(P@SN)
//   M = sqrt(rTr) * rot @ P ; bias = M @ mu
//   out = M @ X - bias   (per-batch 512x3136 GEMM)

#define Cc   512
#define Bb   32
#define HWs  3136
#define MTOTf 100352.0f
#define EPSf 1e-5f
#define NS_ITERS 10

__device__ float g_S [Cc*Cc];
__device__ float g_SN[Cc*Cc];
__device__ float g_P [Cc*Cc];
__device__ float g_T1[Cc*Cc];
__device__ float g_T2[Cc*Cc];
__device__ float g_M [Cc*Cc];
__device__ float g_sum [Cc];
__device__ float g_mean[Cc];
__device__ float g_bias[Cc];
__device__ float g_scal[2];   // [0] = rTr, [1] = sqrt(rTr)

// ---------------------------------------------------------------- zero
__global__ void k_zero() {
    int idx = blockIdx.x * blockDim.x + threadIdx.x;
    if (idx < Cc*Cc) g_S[idx] = 0.f;
    if (idx < Cc)    g_sum[idx] = 0.f;
}

// ---------------------------------------------------------------- channel sums
__global__ void k_sums(const float* __restrict__ X) {
    int c = blockIdx.x, b = blockIdx.y;
    const float4* p = (const float4*)(X + ((size_t)b * Cc + c) * HWs);
    float s = 0.f;
    for (int i = threadIdx.x; i < HWs/4; i += 128) {
        float4 v = p[i];
        s += (v.x + v.y) + (v.z + v.w);
    }
    #pragma unroll
    for (int o = 16; o > 0; o >>= 1) s += __shfl_down_sync(0xffffffffu, s, o);
    __shared__ float sm[4];
    if ((threadIdx.x & 31) == 0) sm[threadIdx.x >> 5] = s;
    __syncthreads();
    if (threadIdx.x == 0) atomicAdd(&g_sum[c], sm[0] + sm[1] + sm[2] + sm[3]);
}

// ---------------------------------------------------------------- Gram: S += Xb Xbᵀ
// 128x128 tile, BK=16, 8x8 split micro-tiles, symmetric pairs only.
__global__ void __launch_bounds__(256) k_gram(const float* __restrict__ X) {
    // decode pair p -> (it, jt), it <= jt, 4 row-tiles
    int p = blockIdx.x;
    int it = 0, rem = p;
    while (rem >= 4 - it) { rem -= 4 - it; it++; }
    int jt = it + rem;
    int b  = blockIdx.y;

    int i0 = it * 128, j0 = jt * 128;
    const float* Xb = X + (size_t)b * Cc * HWs;

    __shared__ float As[16][132];
    __shared__ float Bs[16][132];

    float acc[8][8];
    #pragma unroll
    for (int r = 0; r < 8; r++)
        #pragma unroll
        for (int c = 0; c < 8; c++) acc[r][c] = 0.f;

    int tid = threadIdx.x;
    int tx4 = (tid & 15) * 4;
    int ty4 = (tid >> 4) * 4;

    for (int k0 = 0; k0 < HWs; k0 += 16) {
        #pragma unroll
        for (int l = 0; l < 2; l++) {
            int idx = tid + l * 256;
            int row = idx >> 2;
            int kq  = (idx & 3) * 4;
            float4 va = *(const float4*)(Xb + (size_t)(i0 + row) * HWs + k0 + kq);
            As[kq + 0][row] = va.x; As[kq + 1][row] = va.y;
            As[kq + 2][row] = va.z; As[kq + 3][row] = va.w;
            float4 vb = *(const float4*)(Xb + (size_t)(j0 + row) * HWs + k0 + kq);
            Bs[kq + 0][row] = vb.x; Bs[kq + 1][row] = vb.y;
            Bs[kq + 2][row] = vb.z; Bs[kq + 3][row] = vb.w;
        }
        __syncthreads();
        #pragma unroll
        for (int kk = 0; kk < 16; kk++) {
            float4 a0 = *(const float4*)&As[kk][ty4];
            float4 a1 = *(const float4*)&As[kk][64 + ty4];
            float4 b0 = *(const float4*)&Bs[kk][tx4];
            float4 b1 = *(const float4*)&Bs[kk][64 + tx4];
            float ar[8] = {a0.x,a0.y,a0.z,a0.w,a1.x,a1.y,a1.z,a1.w};
            float br[8] = {b0.x,b0.y,b0.z,b0.w,b1.x,b1.y,b1.z,b1.w};
            #pragma unroll
            for (int r = 0; r < 8; r++)
                #pragma unroll
                for (int c = 0; c < 8; c++)
                    acc[r][c] += ar[r] * br[c];
        }
        __syncthreads();
    }

    bool mirror = (it != jt);
    #pragma unroll
    for (int r = 0; r < 8; r++) {
        int gi = i0 + ((r < 4) ? (ty4 + r) : (64 + ty4 + r - 4));
        #pragma unroll
        for (int c = 0; c < 8; c++) {
            int gj = j0 + ((c < 4) ? (tx4 + c) : (64 + tx4 + c - 4));
            atomicAdd(&g_S[gi * Cc + gj], acc[r][c]);
            if (mirror) atomicAdd(&g_S[gj * Cc + gi], acc[r][c]);
        }
    }
}

// ---------------------------------------------------------------- prep
__global__ void k_prep1() {   // 1 block, 512 threads
    int c = threadIdx.x;
    float mean = g_sum[c] * (1.0f / MTOTf);
    g_mean[c] = mean;
    float t = EPSf + g_S[c * Cc + c] * (1.0f / MTOTf) - mean * mean;
    __shared__ float red[16];
    #pragma unroll
    for (int o = 16; o > 0; o >>= 1) t += __shfl_down_sync(0xffffffffu, t, o);
    if ((c & 31) == 0) red[c >> 5] = t;
    __syncthreads();
    if (c < 16) {
        float v = red[c];
        #pragma unroll
        for (int o = 8; o > 0; o >>= 1) v += __shfl_down_sync(0x0000ffffu, v, o);
        if (c == 0) {
            float rtr = 1.0f / v;
            g_scal[0] = rtr;
            g_scal[1] = sqrtf(rtr);
        }
    }
}

__global__ void k_prep2() {   // grid 1024 x 256
    int idx = blockIdx.x * 256 + threadIdx.x;
    int i = idx >> 9, j = idx & 511;
    float v = g_S[idx] * (1.0f / MTOTf) - g_mean[i] * g_mean[j];
    if (i == j) v += EPSf;
    g_SN[idx] = v * g_scal[0];
    g_P[idx]  = (i == j) ? 1.0f : 0.0f;
}

// ---------------------------------------------------------------- 512^3 GEMM
// D = alpha*(A@B) + beta*Cin ; alpha optionally scaled by *alpha_dev.
// 64x64 tile, BK=32, 4x4 micro, grid (8,8).
__global__ void __launch_bounds__(256) k_gemm512(
    const float* __restrict__ A, const float* __restrict__ Bm,
    const float* __restrict__ Cin, float* __restrict__ D,
    float alpha, float beta, const float* __restrict__ alpha_dev)
{
    int j0 = blockIdx.x * 64;
    int i0 = blockIdx.y * 64;

    __shared__ float As[32][68];
    __shared__ float Bs[32][68];

    float acc[4][4];
    #pragma unroll
    for (int r = 0; r < 4; r++)
        #pragma unroll
        for (int c = 0; c < 4; c++) acc[r][c] = 0.f;

    int tid = threadIdx.x;
    int tx4 = (tid & 15) * 4;
    int ty4 = (tid >> 4) * 4;

    for (int k0 = 0; k0 < Cc; k0 += 32) {
        #pragma unroll
        for (int l = 0; l < 2; l++) {
            int idx = tid + l * 256;
            int row = idx >> 3;
            int kq  = (idx & 7) * 4;
            float4 va = *(const float4*)(A + (size_t)(i0 + row) * Cc + k0 + kq);
            As[kq + 0][row] = va.x; As[kq + 1][row] = va.y;
            As[kq + 2][row] = va.z; As[kq + 3][row] = va.w;
            int krow = idx >> 4;
            int cq   = (idx & 15) * 4;
            *(float4*)&Bs[krow][cq] =
                *(const float4*)(Bm + (size_t)(k0 + krow) * Cc + j0 + cq);
        }
        __syncthreads();
        #pragma unroll
        for (int kk = 0; kk < 32; kk++) {
            float4 av = *(const float4*)&As[kk][ty4];
            float4 bv = *(const float4*)&Bs[kk][tx4];
            float ar[4] = {av.x, av.y, av.z, av.w};
            float br[4] = {bv.x, bv.y, bv.z, bv.w};
            #pragma unroll
            for (int r = 0; r < 4; r++)
                #pragma unroll
                for (int c = 0; c < 4; c++)
                    acc[r][c] += ar[r] * br[c];
        }
        __syncthreads();
    }

    float al = alpha;
    if (alpha_dev) al *= *alpha_dev;
    #pragma unroll
    for (int r = 0; r < 4; r++) {
        int gi = i0 + ty4 + r;
        float4 v;
        v.x = al * acc[r][0]; v.y = al * acc[r][1];
        v.z = al * acc[r][2]; v.w = al * acc[r][3];
        if (Cin) {
            float4 ci = *(const float4*)(Cin + (size_t)gi * Cc + j0 + tx4);
            v.x += beta * ci.x; v.y += beta * ci.y;
            v.z += beta * ci.z; v.w += beta * ci.w;
        }
        *(float4*)(D + (size_t)gi * Cc + j0 + tx4) = v;
    }
}

// ---------------------------------------------------------------- bias = M @ mean
__global__ void k_bias() {   // grid 64 x 256
    int d = blockIdx.x * 8 + (threadIdx.x >> 5);
    int lane = threadIdx.x & 31;
    float s = 0.f;
    for (int c = lane; c < Cc; c += 32) s += g_M[d * Cc + c] * g_mean[c];
    #pragma unroll
    for (int o = 16; o > 0; o >>= 1) s += __shfl_down_sync(0xffffffffu, s, o);
    if (lane == 0) g_bias[d] = s;
}

// ---------------------------------------------------------------- out = M @ X - bias
// per-batch: Out_b(512 x 3136) = M(512x512) @ X_b(512x3136)
// 128x128 tile (hw edge predicated), BK=16, 8x8 split micro.
__global__ void __launch_bounds__(256) k_out(const float* __restrict__ X,
                                             float* __restrict__ Out)
{
    int j0 = blockIdx.x * 128;   // hw tile (25 tiles, last partial)
    int i0 = blockIdx.y * 128;   // d tile (4)
    int b  = blockIdx.z;

    const float* Xb = X + (size_t)b * Cc * HWs;

    __shared__ float As[16][132];
    __shared__ float Bs[16][132];

    float acc[8][8];
    #pragma unroll
    for (int r = 0; r < 8; r++)
        #pragma unroll
        for (int c = 0; c < 8; c++) acc[r][c] = 0.f;

    int tid = threadIdx.x;
    int tx4 = (tid & 15) * 4;
    int ty4 = (tid >> 4) * 4;

    for (int k0 = 0; k0 < Cc; k0 += 16) {
        #pragma unroll
        for (int l = 0; l < 2; l++) {
            int idx = tid + l * 256;
            // A tile (M matrix): transpose into As[k][row]
            int row = idx >> 2;
            int kq  = (idx & 3) * 4;
            float4 va = *(const float4*)(g_M + (size_t)(i0 + row) * Cc + k0 + kq);
            As[kq + 0][row] = va.x; As[kq + 1][row] = va.y;
            As[kq + 2][row] = va.z; As[kq + 3][row] = va.w;
            // B tile (X): already [k][n]
            int krow = idx >> 5;
            int cq   = (idx & 31) * 4;
            int hw   = j0 + cq;
            float4 vb = make_float4(0.f, 0.f, 0.f, 0.f);
            if (hw < HWs)
                vb = *(const float4*)(Xb + (size_t)(k0 + krow) * HWs + hw);
            *(float4*)&Bs[krow][cq] = vb;
        }
        __syncthreads();
        #pragma unroll
        for (int kk = 0; kk < 16; kk++) {
            float4 a0 = *(const float4*)&As[kk][ty4];
            float4 a1 = *(const float4*)&As[kk][64 + ty4];
            float4 b0 = *(const float4*)&Bs[kk][tx4];
            float4 b1 = *(const float4*)&Bs[kk][64 + tx4];
            float ar[8] = {a0.x,a0.y,a0.z,a0.w,a1.x,a1.y,a1.z,a1.w};
            float br[8] = {b0.x,b0.y,b0.z,b0.w,b1.x,b1.y,b1.z,b1.w};
            #pragma unroll
            for (int r = 0; r < 8; r++)
                #pragma unroll
                for (int c = 0; c < 8; c++)
                    acc[r][c] += ar[r] * br[c];
        }
        __syncthreads();
    }

    #pragma unroll
    for (int r = 0; r < 8; r++) {
        int gi = i0 + ((r < 4) ? (ty4 + r) : (64 + ty4 + r - 4));
        float bv = g_bias[gi];
        float* orow = Out + ((size_t)b * Cc + gi) * HWs;
        int c0 = j0 + tx4;
        if (c0 < HWs) {
            float4 v = make_float4(acc[r][0]-bv, acc[r][1]-bv,
                                   acc[r][2]-bv, acc[r][3]-bv);
            *(float4*)(orow + c0) = v;
        }
        int c1 = j0 + 64 + tx4;
        if (c1 < HWs) {
            float4 v = make_float4(acc[r][4]-bv, acc[r][5]-bv,
                                   acc[r][6]-bv, acc[r][7]-bv);
            *(float4*)(orow + c1) = v;
        }
    }
}

// ---------------------------------------------------------------- launch
extern "C" void kernel_launch(void* const* d_in, const int* in_sizes, int n_in,
                              void* d_out, int out_size)
{
    const float* X   = (const float*)d_in[0];
    const float* rot = (const float*)d_in[1];
    float* Out = (float*)d_out;

    float *pP, *pSN, *pT1, *pT2, *pM, *pScal;
    cudaGetSymbolAddress((void**)&pP,   g_P);
    cudaGetSymbolAddress((void**)&pSN,  g_SN);
    cudaGetSymbolAddress((void**)&pT1,  g_T1);
    cudaGetSymbolAddress((void**)&pT2,  g_T2);
    cudaGetSymbolAddress((void**)&pM,   g_M);
    cudaGetSymbolAddress((void**)&pScal, g_scal);

    k_zero<<<(Cc*Cc + 255) / 256, 256>>>();
    k_sums<<<dim3(Cc, Bb), 128>>>(X);
    k_gram<<<dim3(10, Bb), 256>>>(X);
    k_prep1<<<1, 512>>>();
    k_prep2<<<(Cc*Cc) / 256, 256>>>();

    for (int t = 0; t < NS_ITERS; t++) {
        k_gemm512<<<dim3(8, 8), 256>>>(pP,  pP,  nullptr, pT1,  1.0f, 0.0f, nullptr);
        k_gemm512<<<dim3(8, 8), 256>>>(pP,  pSN, nullptr, pT2,  1.0f, 0.0f, nullptr);
        k_gemm512<<<dim3(8, 8), 256>>>(pT1, pT2, pP,      pP,  -0.5f, 1.5f, nullptr);
    }

    // M = sqrt(rTr) * rot @ P
    k_gemm512<<<dim3(8, 8), 256>>>(rot, pP, nullptr, pM, 1.0f, 0.0f, pScal + 1);
    k_bias<<<64, 256>>>();
    k_out<<<dim3(25, 4, Bb), 256>>>(X, Out);
}

// round 10
// speedup vs baseline: 2.1614x; 2.1614x over previous
#include <cuda_runtime.h>
#include <math.h>
#include <stdint.h>

// IterNormRotation: X (32,512,56,56) fp32, rot (1,512,512) fp32, T=10.
//   S = X Xᵀ (Gram over m=B*H*W) via tf32 MMA, sum_c = channel sums
//   Sigma = eps I + S/m - mu muᵀ ; rTr = 1/tr ; SN = Sigma*rTr ; P = I
//   10x NS: P = 1.5P - 0.5 (P@P)@(P@SN)   (fp32 SIMT, dual-output kernel)
//   M = sqrt(rTr) * rot @ P ; bias = M@mu
//   out = M @ X - bias  via tf32 MMA

#define Cc   512
#define Bb   32
#define HWs  3136
#define MTOTf 100352.0f
#define EPSf 1e-5f
#define NS_ITERS 10

#define GP 36     // pitch for [row][k] tiles (k=32)
#define BP 136    // pitch for [k][n] tiles (n=128)

__device__ float g_S [Cc*Cc];
__device__ float g_SN[Cc*Cc];
__device__ float g_P [Cc*Cc];
__device__ float g_T1[Cc*Cc];
__device__ float g_T2[Cc*Cc];
__device__ float g_M [Cc*Cc];
__device__ float g_sum [Cc];
__device__ float g_mean[Cc];
__device__ float g_bias[Cc];
__device__ float g_scal[2];   // [0]=rTr, [1]=sqrt(rTr)

// ---------------------------------------------------------------- helpers
__device__ __forceinline__ uint32_t f2tf(float f) {
    uint32_t u; asm("cvt.rna.tf32.f32 %0, %1;" : "=r"(u) : "f"(f)); return u;
}

__device__ __forceinline__ void mma8(float* d, const uint32_t* a, const uint32_t* b) {
    asm volatile(
        "mma.sync.aligned.m16n8k8.row.col.f32.tf32.tf32.f32 "
        "{%0,%1,%2,%3}, {%4,%5,%6,%7}, {%8,%9}, {%0,%1,%2,%3};\n"
        : "+f"(d[0]), "+f"(d[1]), "+f"(d[2]), "+f"(d[3])
        : "r"(a[0]), "r"(a[1]), "r"(a[2]), "r"(a[3]), "r"(b[0]), "r"(b[1]));
}

// ---------------------------------------------------------------- zero
__global__ void k_zero() {
    int idx = blockIdx.x * blockDim.x + threadIdx.x;
    if (idx < Cc*Cc) g_S[idx] = 0.f;
    if (idx < Cc)    g_sum[idx] = 0.f;
}

// ---------------------------------------------------------------- channel sums
__global__ void k_sums(const float* __restrict__ X) {
    int c = blockIdx.x, b = blockIdx.y;
    const float4* p = (const float4*)(X + ((size_t)b * Cc + c) * HWs);
    float s = 0.f;
    for (int i = threadIdx.x; i < HWs/4; i += 128) {
        float4 v = p[i];
        s += (v.x + v.y) + (v.z + v.w);
    }
    #pragma unroll
    for (int o = 16; o > 0; o >>= 1) s += __shfl_down_sync(0xffffffffu, s, o);
    __shared__ float sm[4];
    if ((threadIdx.x & 31) == 0) sm[threadIdx.x >> 5] = s;
    __syncthreads();
    if (threadIdx.x == 0) atomicAdd(&g_sum[c], sm[0] + sm[1] + sm[2] + sm[3]);
}

// ---------------------------------------------------------------- Gram (tf32 MMA)
// 128x128 tile per (pair, batch), BK=32, 8 warps of 64x32 warp-tiles.
__global__ void __launch_bounds__(256, 2) k_gram(const float* __restrict__ X) {
    int p = blockIdx.x;
    int it = 0, rem = p;
    while (rem >= 4 - it) { rem -= 4 - it; it++; }
    int jt = it + rem;
    int b  = blockIdx.y;

    int i0 = it * 128, j0 = jt * 128;
    const float* Xb = X + (size_t)b * Cc * HWs;

    __shared__ uint32_t As[128 * GP];   // [row 0..127][k 0..31]
    __shared__ uint32_t Bs[128 * GP];

    int tid  = threadIdx.x;
    int lane = tid & 31, warp = tid >> 5;
    int g = lane >> 2, tig = lane & 3;
    int wm = (warp >> 2) * 64;     // warp row base (2 rows of warps)
    int wn = (warp & 3) * 32;      // warp col base (4 cols of warps)

    float acc[4][4][4];
    #pragma unroll
    for (int mt = 0; mt < 4; mt++)
        #pragma unroll
        for (int nt = 0; nt < 4; nt++)
            #pragma unroll
            for (int i = 0; i < 4; i++) acc[mt][nt][i] = 0.f;

    for (int k0 = 0; k0 < HWs; k0 += 32) {
        #pragma unroll
        for (int l = 0; l < 4; l++) {
            int e   = tid + l * 256;          // 1024 float4 slots per tile
            int row = e >> 3;
            int kq  = (e & 7) * 4;
            float4 va = *(const float4*)(Xb + (size_t)(i0 + row) * HWs + k0 + kq);
            *(uint4*)&As[row * GP + kq] =
                make_uint4(f2tf(va.x), f2tf(va.y), f2tf(va.z), f2tf(va.w));
            float4 vb = *(const float4*)(Xb + (size_t)(j0 + row) * HWs + k0 + kq);
            *(uint4*)&Bs[row * GP + kq] =
                make_uint4(f2tf(vb.x), f2tf(vb.y), f2tf(vb.z), f2tf(vb.w));
        }
        __syncthreads();

        #pragma unroll
        for (int ks = 0; ks < 32; ks += 8) {
            uint32_t af[4][4], bf[4][2];
            #pragma unroll
            for (int mt = 0; mt < 4; mt++) {
                int r = wm + mt * 16 + g;
                af[mt][0] = As[r       * GP + ks + tig];
                af[mt][1] = As[(r + 8) * GP + ks + tig];
                af[mt][2] = As[r       * GP + ks + tig + 4];
                af[mt][3] = As[(r + 8) * GP + ks + tig + 4];
            }
            #pragma unroll
            for (int nt = 0; nt < 4; nt++) {
                int c = wn + nt * 8 + g;
                bf[nt][0] = Bs[c * GP + ks + tig];
                bf[nt][1] = Bs[c * GP + ks + tig + 4];
            }
            #pragma unroll
            for (int mt = 0; mt < 4; mt++)
                #pragma unroll
                for (int nt = 0; nt < 4; nt++)
                    mma8(acc[mt][nt], af[mt], bf[nt]);
        }
        __syncthreads();
    }

    bool mirror = (it != jt);
    #pragma unroll
    for (int mt = 0; mt < 4; mt++) {
        int m_ = wm + mt * 16 + g;
        #pragma unroll
        for (int nt = 0; nt < 4; nt++) {
            int n_ = wn + nt * 8 + 2 * tig;
            int gi0 = i0 + m_, gi1 = gi0 + 8;
            int gj0 = j0 + n_, gj1 = gj0 + 1;
            atomicAdd(&g_S[gi0 * Cc + gj0], acc[mt][nt][0]);
            atomicAdd(&g_S[gi0 * Cc + gj1], acc[mt][nt][1]);
            atomicAdd(&g_S[gi1 * Cc + gj0], acc[mt][nt][2]);
            atomicAdd(&g_S[gi1 * Cc + gj1], acc[mt][nt][3]);
            if (mirror) {
                atomicAdd(&g_S[gj0 * Cc + gi0], acc[mt][nt][0]);
                atomicAdd(&g_S[gj1 * Cc + gi0], acc[mt][nt][1]);
                atomicAdd(&g_S[gj0 * Cc + gi1], acc[mt][nt][2]);
                atomicAdd(&g_S[gj1 * Cc + gi1], acc[mt][nt][3]);
            }
        }
    }
}

// ---------------------------------------------------------------- prep
__global__ void k_prep1() {   // 1 block, 512 threads
    int c = threadIdx.x;
    float mean = g_sum[c] * (1.0f / MTOTf);
    g_mean[c] = mean;
    float t = EPSf + g_S[c * Cc + c] * (1.0f / MTOTf) - mean * mean;
    __shared__ float red[16];
    #pragma unroll
    for (int o = 16; o > 0; o >>= 1) t += __shfl_down_sync(0xffffffffu, t, o);
    if ((c & 31) == 0) red[c >> 5] = t;
    __syncthreads();
    if (c < 16) {
        float v = red[c];
        #pragma unroll
        for (int o = 8; o > 0; o >>= 1) v += __shfl_down_sync(0x0000ffffu, v, o);
        if (c == 0) {
            float rtr = 1.0f / v;
            g_scal[0] = rtr;
            g_scal[1] = sqrtf(rtr);
        }
    }
}

__global__ void k_prep2() {   // grid 1024 x 256
    int idx = blockIdx.x * 256 + threadIdx.x;
    int i = idx >> 9, j = idx & 511;
    float v = g_S[idx] * (1.0f / MTOTf) - g_mean[i] * g_mean[j];
    if (i == j) v += EPSf;
    g_SN[idx] = v * g_scal[0];
    g_P[idx]  = (i == j) ? 1.0f : 0.0f;
}

// ---------------------------------------------------------------- 512^3 fp32 GEMM body
__device__ __forceinline__ void gemm512_body(
    const float* __restrict__ A, const float* __restrict__ Bm,
    const float* __restrict__ Cin, float* __restrict__ D,
    float alpha, float beta, const float* __restrict__ alpha_dev,
    int i0, int j0)
{
    __shared__ float As[32][68];
    __shared__ float Bs[32][68];

    float acc[4][4];
    #pragma unroll
    for (int r = 0; r < 4; r++)
        #pragma unroll
        for (int c = 0; c < 4; c++) acc[r][c] = 0.f;

    int tid = threadIdx.x;
    int tx4 = (tid & 15) * 4;
    int ty4 = (tid >> 4) * 4;

    for (int k0 = 0; k0 < Cc; k0 += 32) {
        #pragma unroll
        for (int l = 0; l < 2; l++) {
            int idx = tid + l * 256;
            int row = idx >> 3;
            int kq  = (idx & 7) * 4;
            float4 va = *(const float4*)(A + (size_t)(i0 + row) * Cc + k0 + kq);
            As[kq + 0][row] = va.x; As[kq + 1][row] = va.y;
            As[kq + 2][row] = va.z; As[kq + 3][row] = va.w;
            int krow = idx >> 4;
            int cq   = (idx & 15) * 4;
            *(float4*)&Bs[krow][cq] =
                *(const float4*)(Bm + (size_t)(k0 + krow) * Cc + j0 + cq);
        }
        __syncthreads();
        #pragma unroll
        for (int kk = 0; kk < 32; kk++) {
            float4 av = *(const float4*)&As[kk][ty4];
            float4 bv = *(const float4*)&Bs[kk][tx4];
            float ar[4] = {av.x, av.y, av.z, av.w};
            float br[4] = {bv.x, bv.y, bv.z, bv.w};
            #pragma unroll
            for (int r = 0; r < 4; r++)
                #pragma unroll
                for (int c = 0; c < 4; c++)
                    acc[r][c] += ar[r] * br[c];
        }
        __syncthreads();
    }

    float al = alpha;
    if (alpha_dev) al *= *alpha_dev;
    #pragma unroll
    for (int r = 0; r < 4; r++) {
        int gi = i0 + ty4 + r;
        float4 v;
        v.x = al * acc[r][0]; v.y = al * acc[r][1];
        v.z = al * acc[r][2]; v.w = al * acc[r][3];
        if (Cin) {
            float4 ci = *(const float4*)(Cin + (size_t)gi * Cc + j0 + tx4);
            v.x += beta * ci.x; v.y += beta * ci.y;
            v.z += beta * ci.z; v.w += beta * ci.w;
        }
        *(float4*)(D + (size_t)gi * Cc + j0 + tx4) = v;
    }
}

__global__ void __launch_bounds__(256) k_gemm512(
    const float* __restrict__ A, const float* __restrict__ Bm,
    const float* __restrict__ Cin, float* __restrict__ D,
    float alpha, float beta, const float* __restrict__ alpha_dev)
{
    gemm512_body(A, Bm, Cin, D, alpha, beta, alpha_dev,
                 blockIdx.y * 64, blockIdx.x * 64);
}

// dual: z=0 -> D0 = A@B0, z=1 -> D1 = A@B1  (grid 8,8,2)
__global__ void __launch_bounds__(256) k_gemm512_dual(
    const float* __restrict__ A,
    const float* __restrict__ B0, const float* __restrict__ B1,
    float* __restrict__ D0, float* __restrict__ D1)
{
    gemm512_body(A, blockIdx.z ? B1 : B0, nullptr, blockIdx.z ? D1 : D0,
                 1.0f, 0.0f, nullptr, blockIdx.y * 64, blockIdx.x * 64);
}

// ---------------------------------------------------------------- bias = M @ mean
__global__ void k_bias() {   // grid 64 x 256
    int d = blockIdx.x * 8 + (threadIdx.x >> 5);
    int lane = threadIdx.x & 31;
    float s = 0.f;
    for (int c = lane; c < Cc; c += 32) s += g_M[d * Cc + c] * g_mean[c];
    #pragma unroll
    for (int o = 16; o > 0; o >>= 1) s += __shfl_down_sync(0xffffffffu, s, o);
    if (lane == 0) g_bias[d] = s;
}

// ---------------------------------------------------------------- out = M @ X - bias (tf32 MMA)
// per-batch 512x3136: 128x128 tiles, BK=32, 8 warps of 64x32.
__global__ void __launch_bounds__(256, 2) k_out(const float* __restrict__ X,
                                                float* __restrict__ Out)
{
    int j0 = blockIdx.x * 128;   // hw tile (25, last partial)
    int i0 = blockIdx.y * 128;   // d tile (4)
    int b  = blockIdx.z;

    const float* Xb = X + (size_t)b * Cc * HWs;

    __shared__ uint32_t As[128 * GP];   // M tile  [m][k]
    __shared__ uint32_t Bs[32 * BP];    // X tile  [k][n]

    int tid  = threadIdx.x;
    int lane = tid & 31, warp = tid >> 5;
    int g = lane >> 2, tig = lane & 3;
    int wm = (warp >> 2) * 64;
    int wn = (warp & 3) * 32;

    float acc[4][4][4];
    #pragma unroll
    for (int mt = 0; mt < 4; mt++)
        #pragma unroll
        for (int nt = 0; nt < 4; nt++)
            #pragma unroll
            for (int i = 0; i < 4; i++) acc[mt][nt][i] = 0.f;

    for (int k0 = 0; k0 < Cc; k0 += 32) {
        // A tile: 128 rows x 8 kquads
        #pragma unroll
        for (int l = 0; l < 4; l++) {
            int e   = tid + l * 256;
            int row = e >> 3;
            int kq  = (e & 7) * 4;
            float4 v = *(const float4*)(g_M + (size_t)(i0 + row) * Cc + k0 + kq);
            *(uint4*)&As[row * GP + kq] =
                make_uint4(f2tf(v.x), f2tf(v.y), f2tf(v.z), f2tf(v.w));
        }
        // B tile: 32 krows x 32 nquads
        #pragma unroll
        for (int l = 0; l < 4; l++) {
            int e  = tid + l * 256;
            int kr = e >> 5;
            int nq = (e & 31) * 4;
            int hw = j0 + nq;
            float4 v = make_float4(0.f, 0.f, 0.f, 0.f);
            if (hw < HWs)
                v = *(const float4*)(Xb + (size_t)(k0 + kr) * HWs + hw);
            *(uint4*)&Bs[kr * BP + nq] =
                make_uint4(f2tf(v.x), f2tf(v.y), f2tf(v.z), f2tf(v.w));
        }
        __syncthreads();

        #pragma unroll
        for (int ks = 0; ks < 32; ks += 8) {
            uint32_t af[4][4], bf[4][2];
            #pragma unroll
            for (int mt = 0; mt < 4; mt++) {
                int r = wm + mt * 16 + g;
                af[mt][0] = As[r       * GP + ks + tig];
                af[mt][1] = As[(r + 8) * GP + ks + tig];
                af[mt][2] = As[r       * GP + ks + tig + 4];
                af[mt][3] = As[(r + 8) * GP + ks + tig + 4];
            }
            #pragma unroll
            for (int nt = 0; nt < 4; nt++) {
                int c = wn + nt * 8 + g;
                bf[nt][0] = Bs[(ks + tig)     * BP + c];
                bf[nt][1] = Bs[(ks + tig + 4) * BP + c];
            }
            #pragma unroll
            for (int mt = 0; mt < 4; mt++)
                #pragma unroll
                for (int nt = 0; nt < 4; nt++)
                    mma8(acc[mt][nt], af[mt], bf[nt]);
        }
        __syncthreads();
    }

    #pragma unroll
    for (int mt = 0; mt < 4; mt++) {
        int m_  = wm + mt * 16 + g;
        int gi0 = i0 + m_;
        int gi1 = gi0 + 8;
        float bv0 = g_bias[gi0];
        float bv1 = g_bias[gi1];
        float* orow0 = Out + ((size_t)b * Cc + gi0) * HWs;
        float* orow1 = Out + ((size_t)b * Cc + gi1) * HWs;
        #pragma unroll
        for (int nt = 0; nt < 4; nt++) {
            int col = j0 + wn + nt * 8 + 2 * tig;
            if (col < HWs) {
                float2 v0 = make_float2(acc[mt][nt][0] - bv0, acc[mt][nt][1] - bv0);
                float2 v1 = make_float2(acc[mt][nt][2] - bv1, acc[mt][nt][3] - bv1);
                *(float2*)(orow0 + col) = v0;
                *(float2*)(orow1 + col) = v1;
            }
        }
    }
}

// ---------------------------------------------------------------- launch
extern "C" void kernel_launch(void* const* d_in, const int* in_sizes, int n_in,
                              void* d_out, int out_size)
{
    const float* X   = (const float*)d_in[0];
    const float* rot = (const float*)d_in[1];
    float* Out = (float*)d_out;

    float *pP, *pSN, *pT1, *pT2, *pM, *pScal;
    cudaGetSymbolAddress((void**)&pP,    g_P);
    cudaGetSymbolAddress((void**)&pSN,   g_SN);
    cudaGetSymbolAddress((void**)&pT1,   g_T1);
    cudaGetSymbolAddress((void**)&pT2,   g_T2);
    cudaGetSymbolAddress((void**)&pM,    g_M);
    cudaGetSymbolAddress((void**)&pScal, g_scal);

    k_zero<<<(Cc*Cc + 255) / 256, 256>>>();
    k_sums<<<dim3(Cc, Bb), 128>>>(X);
    k_gram<<<dim3(10, Bb), 256>>>(X);
    k_prep1<<<1, 512>>>();
    k_prep2<<<(Cc*Cc) / 256, 256>>>();

    for (int t = 0; t < NS_ITERS; t++) {
        // T1 = P@P, T2 = P@SN in one launch
        k_gemm512_dual<<<dim3(8, 8, 2), 256>>>(pP, pP, pSN, pT1, pT2);
        // P = 1.5P - 0.5 T1@T2
        k_gemm512<<<dim3(8, 8), 256>>>(pT1, pT2, pP, pP, -0.5f, 1.5f, nullptr);
    }

    // M = sqrt(rTr) * rot @ P
    k_gemm512<<<dim3(8, 8), 256>>>(rot, pP, nullptr, pM, 1.0f, 0.0f, pScal + 1);
    k_bias<<<64, 256>>>();
    k_out<<<dim3(25, 4, Bb), 256>>>(X, Out);
}